// round 14
// baseline (speedup 1.0000x reference)
#include <cuda_runtime.h>
#include <stdint.h>

// Problem constants
#define BB     16
#define NCLS   3
#define CREG   50
#define HH     96
#define WW     320
#define HW     (HH*WW)     // 30720
#define KK     100
#define THRESH 0.2f
#define EPSF   1e-6f

// Selection machinery
#define CAP    8192
#define CAP2   2048
#define NBINS  1280
#define VBASE  0x3E400000u
#define BSHIFT 14

#define XMIN  (-1.3867f)
#define COLL_MARGIN 1e-3f

// Scan-phase partitioning
#define PARTS      4                   // blocks per (b,cls) plane
#define ROWS_PART  (HH/PARTS)          // 24 rows
#define GROUPS_PART (ROWS_PART*(WW/4)) // 1920 float4-groups
#define SCAN_THREADS 512

// Decode-phase partitioning
#define BLKS_PER_IMG 10
#define DETS_PER_BLK (KK/BLKS_PER_IMG) // 10
#define NCH 34
#define NPK_OFF 9

// Global state (zero-initialized at load; select kernel re-zeroes at end of
// each run so every graph replay starts from a clean state)
__device__ int                g_cnt[BB*NCLS];
__device__ unsigned int       g_hist[BB*NCLS][NBINS];
__device__ unsigned long long g_cand[BB*NCLS][CAP];
__device__ unsigned long long g_stage1[BB*NCLS*KK];
__device__ int                g_ridx[BB*KK];     // -1 = masked row
__device__ int                g_rcls[BB*KK];
__device__ float              g_rscore[BB*KK];

__device__ __forceinline__ float sigm(float x) {
    return __fdiv_rn(1.0f, 1.0f + expf(-x));
}
__device__ __forceinline__ float reluf(float x) { return x > 0.f ? x : 0.f; }
__device__ __forceinline__ float clampf(float v, float lo, float hi) {
    return fminf(fmaxf(v, lo), hi);
}
__device__ __forceinline__ float max3(float a, float b, float c) {
    return fmaxf(fmaxf(a, b), c);
}

// ---------------------------------------------------------------------------
// Kernel A: scan. 192 blocks = 4 per (b,cls) plane, 24 rows each.
// NMS logic identical to the validated baseline; candidates appended with
// warp-aggregated GLOBAL atomics (g_cnt) + gmem histogram.
// Ballot safety: GROUPS_PART=1920, stride 512 -> boundary at thread 384,
// a warp boundary, so warps stay convergent at the ballot.
// ---------------------------------------------------------------------------
__global__ __launch_bounds__(SCAN_THREADS)
void scan_kernel(const float* __restrict__ hmp)
{
    const int tid  = threadIdx.x;
    const int lane = tid & 31;
    const int bc   = blockIdx.x / PARTS;
    const int part = blockIdx.x - bc*PARTS;
    const int y0   = part * ROWS_PART;

    const float* base = hmp + (size_t)bc * HW;
    const float4* base4 = (const float4*)base;
    unsigned long long* keys = g_cand[bc];

    const float4 NEG4 = make_float4(-INFINITY, -INFINITY, -INFINITY, -INFINITY);

    for (int g = tid; g < GROUPS_PART; g += SCAN_THREADS) {
        int yl = g / (WW/4);
        int xq = g - yl*(WW/4);
        int y  = y0 + yl;
        int rowg = y*(WW/4);

        float4 Cm = __ldg(base4 + rowg + xq);
        float gmax = fmaxf(fmaxf(Cm.x, Cm.y), fmaxf(Cm.z, Cm.w));

        float m9[4] = {INFINITY, INFINITY, INFINITY, INFINITY};
        if (gmax >= XMIN) {
            float4 Cl = (xq > 0)        ? __ldg(base4 + rowg + xq - 1) : NEG4;
            float4 Cr = (xq < WW/4 - 1) ? __ldg(base4 + rowg + xq + 1) : NEG4;
            float4 Um, Ul, Ur, Dm, Dl, Dr;
            if (y > 0) {
                int rg = rowg - WW/4;
                Um = __ldg(base4 + rg + xq);
                Ul = (xq > 0)        ? __ldg(base4 + rg + xq - 1) : NEG4;
                Ur = (xq < WW/4 - 1) ? __ldg(base4 + rg + xq + 1) : NEG4;
            } else { Um = Ul = Ur = NEG4; }
            if (y < HH-1) {
                int rg = rowg + WW/4;
                Dm = __ldg(base4 + rg + xq);
                Dl = (xq > 0)        ? __ldg(base4 + rg + xq - 1) : NEG4;
                Dr = (xq < WW/4 - 1) ? __ldg(base4 + rg + xq + 1) : NEG4;
            } else { Dm = Dl = Dr = NEG4; }

            float wC0 = max3(Cl.w, Cm.x, Cm.y), wC1 = max3(Cm.x, Cm.y, Cm.z);
            float wC2 = max3(Cm.y, Cm.z, Cm.w), wC3 = max3(Cm.z, Cm.w, Cr.x);
            float wU0 = max3(Ul.w, Um.x, Um.y), wU1 = max3(Um.x, Um.y, Um.z);
            float wU2 = max3(Um.y, Um.z, Um.w), wU3 = max3(Um.z, Um.w, Ur.x);
            float wD0 = max3(Dl.w, Dm.x, Dm.y), wD1 = max3(Dm.x, Dm.y, Dm.z);
            float wD2 = max3(Dm.y, Dm.z, Dm.w), wD3 = max3(Dm.z, Dm.w, Dr.x);

            m9[0] = max3(wU0, wC0, wD0); m9[1] = max3(wU1, wC1, wD1);
            m9[2] = max3(wU2, wC2, wD2); m9[3] = max3(wU3, wC3, wD3);
        }
        float cv[4] = {Cm.x, Cm.y, Cm.z, Cm.w};

        #pragma unroll
        for (int l = 0; l < 4; l++) {
            float v = cv[l];
            bool keep = false;
            float s = 0.f;
            if (gmax >= XMIN && v >= XMIN && m9[l] <= v + COLL_MARGIN) {
                s = sigm(v);
                keep = true;
                if (m9[l] > v) {
                    if (sigm(m9[l]) > s) keep = false;   // rounded-sigmoid tie space
                }
                if (s < THRESH) keep = false;
            }
            unsigned ballot = __ballot_sync(0xFFFFFFFFu, keep);
            if (ballot) {
                int nsel = __popc(ballot);
                int leader = __ffs(ballot) - 1;
                int basepos = 0;
                if (lane == leader) basepos = atomicAdd(&g_cnt[bc], nsel);
                basepos = __shfl_sync(0xFFFFFFFFu, basepos, leader);
                if (keep) {
                    int pos = basepos + __popc(ballot & ((1u << lane) - 1u));
                    if (pos < CAP) {
                        int i = y*WW + xq*4 + l;
                        unsigned vb = __float_as_uint(s);
                        keys[pos] = ((unsigned long long)vb << 32) | (unsigned)(~i);
                        unsigned bin = (vb - VBASE) >> BSHIFT;
                        if (bin >= NBINS) bin = NBINS-1;
                        atomicAdd(&g_hist[bc][bin], 1u);
                    }
                }
            }
        }
    }
}

// ---------------------------------------------------------------------------
// Kernel B: select. 48 blocks (one per plane): pivot from histogram, compact,
// small bitonic sort, write stage-1 top-100. Re-zeroes g_cnt/g_hist at the
// end so the next run (graph replay) starts clean.
// dyn smem = keys2(16KB) + hist(5KB)
// ---------------------------------------------------------------------------
extern __shared__ unsigned char smem_raw[];

__global__ __launch_bounds__(1024)
void select_kernel(void)
{
    unsigned long long* keys2 = (unsigned long long*)smem_raw;        // CAP2
    unsigned int*       hist  = (unsigned int*)(smem_raw + CAP2*8);   // NBINS
    __shared__ int cnt2, pivot;

    const int tid = threadIdx.x;
    const int bc  = blockIdx.x;
    unsigned long long* keys = g_cand[bc];

    if (tid == 0) cnt2 = 0;
    for (int t = tid; t < NBINS; t += 1024) hist[t] = g_hist[bc][t];
    __syncthreads();

    int n = g_cnt[bc]; if (n > CAP) n = CAP;

    if (tid == 0) {
        int cum = 0, pb = 0;
        for (int bnum = NBINS-1; bnum >= 0; bnum--) {
            cum += hist[bnum];
            if (cum >= KK) { pb = bnum; break; }
        }
        pivot = pb;
    }
    __syncthreads();
    const int pv = pivot;

    for (int t = tid; t < n; t += 1024) {
        unsigned long long e = keys[t];
        unsigned vb = (unsigned)(e >> 32);
        unsigned bin = (vb - VBASE) >> BSHIFT;
        if (bin >= NBINS) bin = NBINS-1;
        if ((int)bin >= pv) {
            int pos = atomicAdd(&cnt2, 1);
            if (pos < CAP2) keys2[pos] = e;
        }
    }
    __syncthreads();
    int m = cnt2; if (m > CAP2) m = CAP2;
    int N2 = 128; while (N2 < m) N2 <<= 1;
    for (int t = tid; t < N2; t += 1024) if (t >= m) keys2[t] = 0ull;
    __syncthreads();

    for (int k2 = 2; k2 <= N2; k2 <<= 1) {
        for (int j = k2 >> 1; j > 0; j >>= 1) {
            for (int t = tid; t < N2; t += 1024) {
                int ixj = t ^ j;
                if (ixj > t) {
                    unsigned long long a = keys2[t], b = keys2[ixj];
                    bool desc = ((t & k2) == 0);
                    if (desc ? (a < b) : (a > b)) { keys2[t] = b; keys2[ixj] = a; }
                }
            }
            __syncthreads();
        }
    }

    if (tid < KK) {
        unsigned long long e = keys2[tid];
        unsigned vb  = (unsigned)(e >> 32);
        unsigned idx = ~(unsigned)e;
        g_stage1[bc*KK + tid] = ((unsigned long long)vb << 32) | idx;
    }

    // reset plane state for the next run/replay (deterministic: statics are
    // zero at load; every run leaves them zero again)
    if (tid == 0) g_cnt[bc] = 0;
    for (int t = tid; t < NBINS; t += 1024) g_hist[bc][t] = 0u;
}

// ---------------------------------------------------------------------------
// Kernel C: rank. 16 blocks: 3-way merge of the per-class sorted lists into
// the global top-100 (validated bit-exact in R13), results to gmem.
// ---------------------------------------------------------------------------
__global__ __launch_bounds__(512)
void rank_kernel(void)
{
    __shared__ unsigned long long skeys[NCLS*KK];
    const int tid = threadIdx.x;
    const int b   = blockIdx.x;

    if (tid < NCLS*KK) {
        unsigned long long e = g_stage1[b*NCLS*KK + tid];
        skeys[tid] = (e & 0xFFFFFFFF00000000ull) | (unsigned)(~tid);
    }
    __syncthreads();

    if (tid < NCLS*KK) {
        unsigned long long k = skeys[tid];
        int myclass = tid / KK;
        int rank = tid - myclass*KK;
        #pragma unroll
        for (int o = 0; o < NCLS; o++) {
            if (o == myclass) continue;
            int basei = o*KK;
            int lo = 0, hi = KK;
            while (lo < hi) {
                int mid = (lo + hi) >> 1;
                if (skeys[basei + mid] > k) lo = mid + 1; else hi = mid;
            }
            rank += lo;
        }
        if (rank < KK) {
            unsigned long long e = g_stage1[b*NCLS*KK + tid];
            float score = __uint_as_float((unsigned)(e >> 32));
            g_rscore[b*KK + rank] = score;
            g_rcls[b*KK + rank]   = myclass;
            g_ridx[b*KK + rank]   = (score >= THRESH) ? (int)(e & 0xFFFFFFFFull) : -1;
        }
    }
}

// ---------------------------------------------------------------------------
// Kernel D: decode. 160 blocks (10 per image, 10 detections each): wide
// cooperative gather into smem, then per-detection MonoFlex math (unchanged).
// ---------------------------------------------------------------------------
__global__ __launch_bounds__(256)
void decode_kernel(const float* __restrict__ reg,
                   const float* __restrict__ calib,
                   const float* __restrict__ pad_size,
                   const float* __restrict__ dim_mean,
                   float* __restrict__ out)
{
    __shared__ float pois[DETS_PER_BLK][NCH+1];
    __shared__ int   sidx[DETS_PER_BLK];

    const int tid   = threadIdx.x;
    const int b     = blockIdx.x / BLKS_PER_IMG;
    const int chunk = blockIdx.x - b*BLKS_PER_IMG;
    const int dbase = chunk * DETS_PER_BLK;

    if (tid < DETS_PER_BLK) sidx[tid] = g_ridx[b*KK + dbase + tid];
    __syncthreads();

    const float* regb = reg + (size_t)b*CREG*HW;
    for (int u = tid; u < DETS_PER_BLK*NCH; u += 256) {
        int dl = u / NCH;
        int c  = u - dl*NCH;
        int idx = sidx[dl];
        if (idx >= 0) {
            int chan = (c < NPK_OFF) ? c : (c + 16);
            pois[dl][c] = __ldg(regb + (size_t)chan*HW + idx);
        }
    }
    __syncthreads();

    if (tid < DETS_PER_BLK) {
        int dglob = dbase + tid;
        float* row = out + (size_t)(b*KK + dglob) * 13;
        int idx = sidx[tid];
        if (idx < 0) {
            #pragma unroll
            for (int c = 0; c < 13; c++) row[c] = 0.f;
        } else {
            float score = g_rscore[b*KK + dglob];
            int   cls   = g_rcls[b*KK + dglob];
            const float* pc = &pois[tid][0];
            const float* pk = &pois[tid][NPK_OFF];

            float xs = (float)(idx % WW);
            float ys = (float)(idx / WW);
            float fu = __ldg(calib + b*4 + 0), cu = __ldg(calib + b*4 + 1);
            float fv = __ldg(calib + b*4 + 2), cv = __ldg(calib + b*4 + 3);
            float pd0 = __ldg(pad_size + b*2 + 0), pd1 = __ldg(pad_size + b*2 + 1);

            float d0 = expf(pc[6]) * __ldg(dim_mean + cls*3 + 0);
            float d1 = expf(pc[7]) * __ldg(dim_mean + cls*3 + 1);
            float d2 = expf(pc[8]) * __ldg(dim_mean + cls*3 + 2);
            float h3d = d1;

            float sg = sigm(pk[23]);
            float dd = clampf(__fdiv_rn(1.0f, sg) - 1.0f, 0.1f, 100.0f);

            float fuh = fu * h3d;
            float dctr = clampf(fuh/(reluf(pk[17]-pk[19])*4.0f + EPSF), 0.1f, 100.0f);
            float a02 = fuh/(reluf(pk[1]-pk[9])*4.0f + EPSF);
            float b02 = fuh/(reluf(pk[5]-pk[13])*4.0f + EPSF);
            float d02 = clampf((a02 + b02)*0.5f, 0.1f, 100.0f);
            float a13 = fuh/(reluf(pk[3]-pk[11])*4.0f + EPSF);
            float b13 = fuh/(reluf(pk[7]-pk[15])*4.0f + EPSF);
            float d13 = clampf((a13 + b13)*0.5f, 0.1f, 100.0f);

            float u0 = expf(pk[24]);
            float u1 = expf(pk[20]), u2 = expf(pk[21]), u3 = expf(pk[22]);
            float w0 = 1.0f/u0, w1 = 1.0f/u1, w2 = 1.0f/u2, w3 = 1.0f/u3;
            float S  = w0 + w1 + w2 + w3;
            float wn0 = w0/S, wn1 = w1/S, wn2 = w2/S, wn3 = w3/S;
            float depth = dd*wn0 + dctr*wn1 + d02*wn2 + d13*wn3;
            float derr  = wn0*u0 + wn1*u1 + wn2*u2 + wn3*u3;

            float bx0 = clampf((xs - reluf(pc[0]))*4.0f - pd0, 0.0f, 1279.0f);
            float by0 = clampf((ys - reluf(pc[1]))*4.0f - pd1, 0.0f, 383.0f);
            float bx1 = clampf((xs + reluf(pc[2]))*4.0f - pd0, 0.0f, 1279.0f);
            float by1 = clampf((ys + reluf(pc[3]))*4.0f - pd1, 0.0f, 383.0f);

            float px = (xs + pc[4])*4.0f - pd0;
            float py = (ys + pc[5])*4.0f - pd1;
            float x3 = (px - cu)*depth/fu;
            float y3 = (py - cv)*depth/fv;

            row[0]  = (float)cls; row[1]  = score;
            row[2]  = bx0;        row[3]  = by0;
            row[4]  = bx1;        row[5]  = by1;
            row[6]  = d0;         row[7]  = d1;   row[8] = d2;
            row[9]  = x3;         row[10] = y3;   row[11] = depth;
            row[12] = derr;
        }
    }
}

extern "C" void kernel_launch(void* const* d_in, const int* in_sizes, int n_in,
                              void* d_out, int out_size)
{
    const float* hmp   = (const float*)d_in[0];
    const float* reg   = (const float*)d_in[1];
    const float* calib = (const float*)d_in[2];
    const float* pads  = (const float*)d_in[3];
    const float* dimm  = (const float*)d_in[4];
    float* out = (float*)d_out;

    const int shbytes = CAP2*8 + NBINS*4;     // 21504 (<48KB, no opt-in)
    scan_kernel<<<BB*NCLS*PARTS, SCAN_THREADS>>>(hmp);
    select_kernel<<<BB*NCLS, 1024, shbytes>>>();
    rank_kernel<<<BB, 512>>>();
    decode_kernel<<<BB*BLKS_PER_IMG, 256>>>(reg, calib, pads, dimm, out);
}